// round 1
// baseline (speedup 1.0000x reference)
#include <cuda_runtime.h>
#include <math.h>

// Problem constants
#define Bb   2
#define Ss   2048
#define Hh   1024
#define NHh  16
#define HDd  64
#define TH   3072          // 3*H
#define M1   4096          // B*S
#define NBH  32            // B*NH

// Scratch (static device globals: allocation-free per harness rules)
__device__ float g_qkv[(size_t)M1 * TH];                 // 50 MB
__device__ float g_scores[(size_t)NBH * Ss * Ss];        // 512 MB
__device__ float g_attn[(size_t)M1 * Hh];                // 16 MB

// ---------------------------------------------------------------------------
// Generic NT GEMM: C[m][n] = alpha * sum_k A[m][k]*B[n][k]
// BM=BN=128, BK=16, 256 threads, 8x8 per thread (split 4+4 register mapping).
// Batched over blockIdx.z with (b = z>>4, h = z&15) offset decomposition.
// Requires: M,N multiples of 128; K multiple of 16; all row bases 16B aligned.
// ---------------------------------------------------------------------------
__global__ __launch_bounds__(256) void gemm_nt(
    const float* __restrict__ A, const float* __restrict__ Bm, float* __restrict__ C,
    int M, int N, int K, int lda, int ldb, int ldc,
    long aOffB, long aOffH, long bOffB, long bOffH, long cOffZ, float alpha)
{
    __shared__ float As[16][128];
    __shared__ float Bs[16][128];

    int z = blockIdx.z;
    const float* Ab = A + (long)(z >> 4) * aOffB + (long)(z & 15) * aOffH;
    const float* Bq = Bm + (long)(z >> 4) * bOffB + (long)(z & 15) * bOffH;
    float* Cb = C + (long)z * cOffZ;

    int row0 = blockIdx.y * 128;
    int col0 = blockIdx.x * 128;
    int tid  = threadIdx.x;
    int tx = tid & 15, ty = tid >> 4;

    float acc[8][8];
#pragma unroll
    for (int i = 0; i < 8; i++)
#pragma unroll
        for (int j = 0; j < 8; j++) acc[i][j] = 0.f;

    for (int k0 = 0; k0 < K; k0 += 16) {
#pragma unroll
        for (int it = 0; it < 2; it++) {
            int idx = tid * 2 + it;            // 0..511
            int r   = idx >> 2;                // 0..127
            int kv  = (idx & 3) * 4;           // 0,4,8,12
            float4 v = *reinterpret_cast<const float4*>(Ab + (long)(row0 + r) * lda + k0 + kv);
            As[kv + 0][r] = v.x; As[kv + 1][r] = v.y; As[kv + 2][r] = v.z; As[kv + 3][r] = v.w;
        }
#pragma unroll
        for (int it = 0; it < 2; it++) {
            int idx = tid * 2 + it;
            int r   = idx >> 2;
            int kv  = (idx & 3) * 4;
            float4 v = *reinterpret_cast<const float4*>(Bq + (long)(col0 + r) * ldb + k0 + kv);
            Bs[kv + 0][r] = v.x; Bs[kv + 1][r] = v.y; Bs[kv + 2][r] = v.z; Bs[kv + 3][r] = v.w;
        }
        __syncthreads();

#pragma unroll
        for (int kk = 0; kk < 16; kk++) {
            float4 a0 = *reinterpret_cast<const float4*>(&As[kk][ty * 4]);
            float4 a1 = *reinterpret_cast<const float4*>(&As[kk][64 + ty * 4]);
            float4 b0 = *reinterpret_cast<const float4*>(&Bs[kk][tx * 4]);
            float4 b1 = *reinterpret_cast<const float4*>(&Bs[kk][64 + tx * 4]);
            float ra[8] = {a0.x, a0.y, a0.z, a0.w, a1.x, a1.y, a1.z, a1.w};
            float rb[8] = {b0.x, b0.y, b0.z, b0.w, b1.x, b1.y, b1.z, b1.w};
#pragma unroll
            for (int i = 0; i < 8; i++)
#pragma unroll
                for (int j = 0; j < 8; j++) acc[i][j] += ra[i] * rb[j];
        }
        __syncthreads();
    }

#pragma unroll
    for (int ih = 0; ih < 2; ih++)
#pragma unroll
        for (int i = 0; i < 4; i++) {
            int r = row0 + ih * 64 + ty * 4 + i;
#pragma unroll
            for (int jh = 0; jh < 2; jh++) {
                int c = col0 + jh * 64 + tx * 4;
                float4 v;
                v.x = acc[ih * 4 + i][jh * 4 + 0] * alpha;
                v.y = acc[ih * 4 + i][jh * 4 + 1] * alpha;
                v.z = acc[ih * 4 + i][jh * 4 + 2] * alpha;
                v.w = acc[ih * 4 + i][jh * 4 + 3] * alpha;
                *reinterpret_cast<float4*>(Cb + (long)r * ldc + c) = v;
            }
        }
}

// ---------------------------------------------------------------------------
// RoPE in-place on q,k inside g_qkv. One thread handles pair (d, d+32) for
// both q and k at one (b,s,h). fp32 path mirrors jax's fp32 arithmetic.
// ---------------------------------------------------------------------------
__global__ __launch_bounds__(256) void rope_kernel(float* __restrict__ qkv)
{
    int idx = blockIdx.x * blockDim.x + threadIdx.x;   // < 2^21
    int d = idx & 31;
    int h = (idx >> 5) & 15;
    int s = (idx >> 9) & 2047;
    int b = idx >> 20;

    float invf = 1.0f / powf(10000.0f, (float)d / 32.0f);
    float phase = (float)s * invf;
    float sn, cs;
    sincosf(phase, &sn, &cs);

    long base = ((long)(b * Ss + s)) * TH + h * 64 + d;
    // q
    {
        float x1 = qkv[base];
        float x2 = qkv[base + 32];
        qkv[base]      = x1 * cs - x2 * sn;
        qkv[base + 32] = x2 * cs + x1 * sn;
    }
    // k
    {
        float x1 = qkv[base + Hh];
        float x2 = qkv[base + Hh + 32];
        qkv[base + Hh]      = x1 * cs - x2 * sn;
        qkv[base + Hh + 32] = x2 * cs + x1 * sn;
    }
}

// ---------------------------------------------------------------------------
// Row softmax over g_scores, in place. One block per row (2048 elems).
// ---------------------------------------------------------------------------
__global__ __launch_bounds__(256) void softmax_kernel(float* __restrict__ sc)
{
    long row = blockIdx.x;
    float4* p = reinterpret_cast<float4*>(sc + row * Ss);
    int tid = threadIdx.x;

    float4 a = p[tid];
    float4 b = p[tid + 256];

    __shared__ float red[8];
    float m = fmaxf(fmaxf(fmaxf(a.x, a.y), fmaxf(a.z, a.w)),
                    fmaxf(fmaxf(b.x, b.y), fmaxf(b.z, b.w)));
#pragma unroll
    for (int o = 16; o; o >>= 1) m = fmaxf(m, __shfl_xor_sync(0xffffffffu, m, o));
    if ((tid & 31) == 0) red[tid >> 5] = m;
    __syncthreads();
    m = red[0];
#pragma unroll
    for (int i = 1; i < 8; i++) m = fmaxf(m, red[i]);
    __syncthreads();

    a.x = expf(a.x - m); a.y = expf(a.y - m); a.z = expf(a.z - m); a.w = expf(a.w - m);
    b.x = expf(b.x - m); b.y = expf(b.y - m); b.z = expf(b.z - m); b.w = expf(b.w - m);

    float s = (a.x + a.y + a.z + a.w) + (b.x + b.y + b.z + b.w);
#pragma unroll
    for (int o = 16; o; o >>= 1) s += __shfl_xor_sync(0xffffffffu, s, o);
    if ((tid & 31) == 0) red[tid >> 5] = s;
    __syncthreads();
    s = 0.f;
#pragma unroll
    for (int i = 0; i < 8; i++) s += red[i];

    float inv = 1.0f / s;
    a.x *= inv; a.y *= inv; a.z *= inv; a.w *= inv;
    b.x *= inv; b.y *= inv; b.z *= inv; b.w *= inv;
    p[tid] = a;
    p[tid + 256] = b;
}

// ---------------------------------------------------------------------------
// PV: O_z[q][d] = sum_k P_z[q][k] * V_z[k][d].  BM=64, BN=64(=HD), BK=32.
// grid (S/64, 32). Writes into g_attn laid out [B*S][H] (head-interleaved).
// ---------------------------------------------------------------------------
__global__ __launch_bounds__(256) void pv_kernel(
    const float* __restrict__ P, const float* __restrict__ qkv, float* __restrict__ attn)
{
    __shared__ float Ps[32][64];   // [k][row], transposed on store
    __shared__ float Vs[32][64];   // [k][n]

    int z = blockIdx.y;
    int b = z >> 4, h = z & 15;
    const float* Pz = P + (long)z * Ss * Ss;
    int row0 = blockIdx.x * 64;
    int tid = threadIdx.x;
    int tx = tid & 15, ty = tid >> 4;

    float acc[4][4];
#pragma unroll
    for (int i = 0; i < 4; i++)
#pragma unroll
        for (int j = 0; j < 4; j++) acc[i][j] = 0.f;

    for (int kt = 0; kt < Ss; kt += 32) {
#pragma unroll
        for (int it = 0; it < 2; it++) {
            int idx = tid * 2 + it;            // 0..511
            int r   = idx >> 3;                // 0..63
            int kv  = (idx & 7) * 4;           // 0..28
            float4 v = *reinterpret_cast<const float4*>(Pz + (long)(row0 + r) * Ss + kt + kv);
            Ps[kv + 0][r] = v.x; Ps[kv + 1][r] = v.y; Ps[kv + 2][r] = v.z; Ps[kv + 3][r] = v.w;
        }
#pragma unroll
        for (int it = 0; it < 2; it++) {
            int idx = tid * 2 + it;
            int r   = idx >> 4;                // 0..31
            int nv  = (idx & 15) * 4;          // 0..60
            float4 v = *reinterpret_cast<const float4*>(
                qkv + ((long)(b * Ss + kt + r)) * TH + 2 * Hh + h * 64 + nv);
            *reinterpret_cast<float4*>(&Vs[r][nv]) = v;
        }
        __syncthreads();

#pragma unroll
        for (int kk = 0; kk < 32; kk++) {
            float4 pr = *reinterpret_cast<const float4*>(&Ps[kk][ty * 4]);
            float4 vr = *reinterpret_cast<const float4*>(&Vs[kk][tx * 4]);
            float ra[4] = {pr.x, pr.y, pr.z, pr.w};
            float rb[4] = {vr.x, vr.y, vr.z, vr.w};
#pragma unroll
            for (int i = 0; i < 4; i++)
#pragma unroll
                for (int j = 0; j < 4; j++) acc[i][j] += ra[i] * rb[j];
        }
        __syncthreads();
    }

#pragma unroll
    for (int i = 0; i < 4; i++) {
        long r = (long)(b * Ss + row0 + ty * 4 + i);
        float4 v;
        v.x = acc[i][0]; v.y = acc[i][1]; v.z = acc[i][2]; v.w = acc[i][3];
        *reinterpret_cast<float4*>(attn + r * Hh + h * 64 + tx * 4) = v;
    }
}

// ---------------------------------------------------------------------------
extern "C" void kernel_launch(void* const* d_in, const int* in_sizes, int n_in,
                              void* d_out, int out_size)
{
    const float* x     = (const float*)d_in[0];   // [2,2048,1024]
    const float* w_qkv = (const float*)d_in[1];   // [3072,1024]
    const float* w_out = (const float*)d_in[2];   // [1024,1024]
    float* out = (float*)d_out;                   // [2,2048,1024]

    float* qkv;   cudaGetSymbolAddress((void**)&qkv,   g_qkv);
    float* sco;   cudaGetSymbolAddress((void**)&sco,   g_scores);
    float* attn;  cudaGetSymbolAddress((void**)&attn,  g_attn);

    // 1) qkv = x @ w_qkv^T     (4096 x 3072 x 1024)
    gemm_nt<<<dim3(TH / 128, M1 / 128, 1), 256>>>(
        x, w_qkv, qkv, M1, TH, Hh, Hh, Hh, TH,
        0, 0, 0, 0, 0, 1.0f);

    // 2) RoPE on q,k in place
    rope_kernel<<<(Bb * Ss * NHh * 32) / 256, 256>>>(qkv);

    // 3) scores = scale * Q K^T, batched over 32 (b,h)
    gemm_nt<<<dim3(Ss / 128, Ss / 128, NBH), 256>>>(
        qkv, qkv + Hh, sco, Ss, Ss, HDd, TH, TH, Ss,
        (long)Ss * TH, 64, (long)Ss * TH, 64, (long)Ss * Ss, 0.125f);

    // 4) softmax rows
    softmax_kernel<<<NBH * Ss, 256>>>(sco);

    // 5) O = P V, batched
    pv_kernel<<<dim3(Ss / 64, NBH), 256>>>(sco, qkv, attn);

    // 6) out = attn @ w_out^T  (4096 x 1024 x 1024)
    gemm_nt<<<dim3(Hh / 128, M1 / 128, 1), 256>>>(
        attn, w_out, out, M1, Hh, Hh, Hh, Hh, Hh,
        0, 0, 0, 0, 0, 1.0f);
}

// round 6
// speedup vs baseline: 1.7045x; 1.7045x over previous
#include <cuda_runtime.h>
#include <cuda_bf16.h>
#include <math.h>
#include <stdint.h>

// Problem constants
#define Bb   2
#define Ss   2048
#define Hh   1024
#define NHh  16
#define HDd  64
#define TH   3072          // 3*H
#define M1   4096          // B*S
#define NBH  32            // B*NH

// Scratch (static device globals)
__device__ float g_qkv[(size_t)M1 * TH];                 // 50 MB
__device__ float g_scores[(size_t)NBH * Ss * Ss];        // 512 MB
__device__ float g_attn[(size_t)M1 * Hh];                // 16 MB
__device__ float g_vt[(size_t)NBH * 64 * Ss];            // 16 MB  V transposed [z][d][k]

// ---------------------------------------------------------------------------
// Helpers
// ---------------------------------------------------------------------------
__device__ __forceinline__ uint32_t smem_u32(const void* p) {
    uint32_t a;
    asm("{ .reg .u64 t; cvta.to.shared.u64 t, %1; cvt.u32.u64 %0, t; }"
        : "=r"(a) : "l"(p));
    return a;
}

__device__ __forceinline__ void ldm4(uint32_t& r0, uint32_t& r1, uint32_t& r2, uint32_t& r3,
                                     uint32_t addr) {
    asm volatile("ldmatrix.sync.aligned.m8n8.x4.shared.b16 {%0,%1,%2,%3}, [%4];"
                 : "=r"(r0), "=r"(r1), "=r"(r2), "=r"(r3) : "r"(addr));
}

__device__ __forceinline__ void mma16816(float* c, const uint32_t* a, const uint32_t* b) {
    asm volatile(
        "mma.sync.aligned.m16n8k16.row.col.f32.bf16.bf16.f32 "
        "{%0,%1,%2,%3}, {%4,%5,%6,%7}, {%8,%9}, {%0,%1,%2,%3};"
        : "+f"(c[0]), "+f"(c[1]), "+f"(c[2]), "+f"(c[3])
        : "r"(a[0]), "r"(a[1]), "r"(a[2]), "r"(a[3]), "r"(b[0]), "r"(b[1]));
}

// fp32 -> (hi,lo) bf16 split of a float4, packed into two uint2 (bf16x2 pairs)
__device__ __forceinline__ void split_f4(float4 v, uint2& hh, uint2& ll) {
    __nv_bfloat16 h0 = __float2bfloat16_rn(v.x), h1 = __float2bfloat16_rn(v.y);
    __nv_bfloat16 h2 = __float2bfloat16_rn(v.z), h3 = __float2bfloat16_rn(v.w);
    __nv_bfloat16 l0 = __float2bfloat16_rn(v.x - __bfloat162float(h0));
    __nv_bfloat16 l1 = __float2bfloat16_rn(v.y - __bfloat162float(h1));
    __nv_bfloat16 l2 = __float2bfloat16_rn(v.z - __bfloat162float(h2));
    __nv_bfloat16 l3 = __float2bfloat16_rn(v.w - __bfloat162float(h3));
    hh.x = ((uint32_t)__bfloat16_as_ushort(h1) << 16) | __bfloat16_as_ushort(h0);
    hh.y = ((uint32_t)__bfloat16_as_ushort(h3) << 16) | __bfloat16_as_ushort(h2);
    ll.x = ((uint32_t)__bfloat16_as_ushort(l1) << 16) | __bfloat16_as_ushort(l0);
    ll.y = ((uint32_t)__bfloat16_as_ushort(l3) << 16) | __bfloat16_as_ushort(l2);
}

// ---------------------------------------------------------------------------
// Batched NT GEMM on mma.sync bf16 with 3-term fp32 emulation.
// C[m][n] = alpha * sum_k A[m][k]*B[n][k]
// CTA 128 x BN, BK=32, 256 threads = 8 warps (4 m x 2 n).
// SMEM tiles padded to 40 bf16/row (80B pitch -> conflict-free ldmatrix).
// Requires M%128==0, N%BN==0, K%32==0, rows 16B-aligned.
// ---------------------------------------------------------------------------
template<int BN>
__global__ __launch_bounds__(256) void gemm_mma(
    const float* __restrict__ A, const float* __restrict__ Bm, float* __restrict__ C,
    int K, int lda, int ldb, int ldc,
    long aOffB, long aOffH, long bOffB, long bOffH, long cOffB, long cOffH,
    float alpha)
{
    constexpr int WN   = BN / 2;     // warp n-tile
    constexpr int NSUB = BN / 16;    // 8-wide n-subtiles per warp
    constexpr int NB4  = BN / 32;    // B float4 loads per thread
    constexpr int P    = 40;         // smem pitch in bf16 elements

    __shared__ __align__(16) uint16_t sAhi[128 * P];
    __shared__ __align__(16) uint16_t sAlo[128 * P];
    __shared__ __align__(16) uint16_t sBhi[BN * P];
    __shared__ __align__(16) uint16_t sBlo[BN * P];

    const int tid = threadIdx.x;
    const int t   = tid & 31;
    const int wid = tid >> 5;
    const int warp_m = wid & 3;         // 0..3  -> m offset 32*warp_m
    const int warp_n = wid >> 2;        // 0..1  -> n offset WN*warp_n

    const int z = blockIdx.z, zb = z >> 4, zh = z & 15;
    const float* At = A + (long)zb * aOffB + (long)zh * aOffH + (long)blockIdx.y * 128 * lda;
    const float* Bt = Bm + (long)zb * bOffB + (long)zh * bOffH + (long)blockIdx.x * BN * ldb;
    float* Cb = C + (long)zb * cOffB + (long)zh * cOffH;

    const uint32_t uAhi = smem_u32(sAhi), uAlo = smem_u32(sAlo);
    const uint32_t uBhi = smem_u32(sBhi), uBlo = smem_u32(sBlo);

    // ldmatrix lane address components
    const int aRow = (t & 7) + ((t >> 3) & 1) * 8;   // row within 16-row A subtile
    const int aCol = (t >> 4) << 3;                   // 0 or 8
    const int bRow = (t & 7) + ((t >> 4) << 3);       // row within 16-row B pair
    const int bCol = ((t >> 3) & 1) << 3;             // 0 or 8

    float acc[2][NSUB][4];
#pragma unroll
    for (int i = 0; i < 2; i++)
#pragma unroll
        for (int j = 0; j < NSUB; j++)
#pragma unroll
            for (int q = 0; q < 4; q++) acc[i][j][q] = 0.f;

    float4 aPf[4], bPf[NB4];
    // Prefetch K-block 0
#pragma unroll
    for (int i = 0; i < 4; i++) {
        int id = tid + 256 * i;
        aPf[i] = *(const float4*)(At + (long)(id >> 3) * lda + ((id & 7) << 2));
    }
#pragma unroll
    for (int i = 0; i < NB4; i++) {
        int id = tid + 256 * i;
        bPf[i] = *(const float4*)(Bt + (long)(id >> 3) * ldb + ((id & 7) << 2));
    }

    const int niter = K / 32;
    for (int it = 0; it < niter; ++it) {
        __syncthreads();   // all warps done reading smem from previous block

        // Split-store current block
#pragma unroll
        for (int i = 0; i < 4; i++) {
            int id = tid + 256 * i;
            int e = (id >> 3) * P + ((id & 7) << 2);
            uint2 hh, ll;
            split_f4(aPf[i], hh, ll);
            *(uint2*)&sAhi[e] = hh;
            *(uint2*)&sAlo[e] = ll;
        }
#pragma unroll
        for (int i = 0; i < NB4; i++) {
            int id = tid + 256 * i;
            int e = (id >> 3) * P + ((id & 7) << 2);
            uint2 hh, ll;
            split_f4(bPf[i], hh, ll);
            *(uint2*)&sBhi[e] = hh;
            *(uint2*)&sBlo[e] = ll;
        }
        __syncthreads();

        // Prefetch next block (latency hidden by the mma work below)
        if (it + 1 < niter) {
            const float* An = At + (it + 1) * 32;
            const float* Bn = Bt + (it + 1) * 32;
#pragma unroll
            for (int i = 0; i < 4; i++) {
                int id = tid + 256 * i;
                aPf[i] = *(const float4*)(An + (long)(id >> 3) * lda + ((id & 7) << 2));
            }
#pragma unroll
            for (int i = 0; i < NB4; i++) {
                int id = tid + 256 * i;
                bPf[i] = *(const float4*)(Bn + (long)(id >> 3) * ldb + ((id & 7) << 2));
            }
        }

        // Compute: 2 k-steps of 16
#pragma unroll
        for (int ks = 0; ks < 2; ks++) {
            const int k0 = ks * 16;
            uint32_t ah[2][4], al[2][4];
#pragma unroll
            for (int ms = 0; ms < 2; ms++) {
                int mbase = warp_m * 32 + ms * 16;
                uint32_t e = (uint32_t)((mbase + aRow) * P + k0 + aCol) * 2;
                ldm4(ah[ms][0], ah[ms][1], ah[ms][2], ah[ms][3], uAhi + e);
                ldm4(al[ms][0], al[ms][1], al[ms][2], al[ms][3], uAlo + e);
            }
            uint32_t bh[NSUB][2], bl[NSUB][2];
#pragma unroll
            for (int p = 0; p < NSUB / 2; p++) {
                int nbase = warp_n * WN + p * 16;
                uint32_t e = (uint32_t)((nbase + bRow) * P + k0 + bCol) * 2;
                ldm4(bh[2 * p][0], bh[2 * p][1], bh[2 * p + 1][0], bh[2 * p + 1][1], uBhi + e);
                ldm4(bl[2 * p][0], bl[2 * p][1], bl[2 * p + 1][0], bl[2 * p + 1][1], uBlo + e);
            }
#pragma unroll
            for (int ms = 0; ms < 2; ms++)
#pragma unroll
                for (int ns = 0; ns < NSUB; ns++) {
                    mma16816(acc[ms][ns], ah[ms], bh[ns]);   // hi*hi
                    mma16816(acc[ms][ns], ah[ms], bl[ns]);   // hi*lo
                    mma16816(acc[ms][ns], al[ms], bh[ns]);   // lo*hi
                }
        }
    }

    // Epilogue: direct stores, fragment layout c0,c1 @ (r, c..c+1), c2,c3 @ (r+8)
    const int rBase = blockIdx.y * 128 + warp_m * 32;
    const long cBase = (long)blockIdx.x * BN + warp_n * WN;
#pragma unroll
    for (int ms = 0; ms < 2; ms++) {
        int r0 = rBase + ms * 16 + (t >> 2);
#pragma unroll
        for (int ns = 0; ns < NSUB; ns++) {
            long c0 = cBase + ns * 8 + (t & 3) * 2;
            float2 v0 = make_float2(acc[ms][ns][0] * alpha, acc[ms][ns][1] * alpha);
            float2 v1 = make_float2(acc[ms][ns][2] * alpha, acc[ms][ns][3] * alpha);
            *(float2*)(Cb + (long)r0 * ldc + c0)       = v0;
            *(float2*)(Cb + (long)(r0 + 8) * ldc + c0) = v1;
        }
    }
}

// ---------------------------------------------------------------------------
// RoPE in-place on q,k inside g_qkv (fp32, mirrors jax fp32 arithmetic).
// ---------------------------------------------------------------------------
__global__ __launch_bounds__(256) void rope_kernel(float* __restrict__ qkv)
{
    int idx = blockIdx.x * blockDim.x + threadIdx.x;
    int d = idx & 31;
    int h = (idx >> 5) & 15;
    int s = (idx >> 9) & 2047;
    int b = idx >> 20;

    float invf = 1.0f / powf(10000.0f, (float)d / 32.0f);
    float phase = (float)s * invf;
    float sn, cs;
    sincosf(phase, &sn, &cs);

    long base = ((long)(b * Ss + s)) * TH + h * 64 + d;
    {
        float x1 = qkv[base];
        float x2 = qkv[base + 32];
        qkv[base]      = x1 * cs - x2 * sn;
        qkv[base + 32] = x2 * cs + x1 * sn;
    }
    {
        float x1 = qkv[base + Hh];
        float x2 = qkv[base + Hh + 32];
        qkv[base + Hh]      = x1 * cs - x2 * sn;
        qkv[base + Hh + 32] = x2 * cs + x1 * sn;
    }
}

// ---------------------------------------------------------------------------
// Transpose V into Vt[z][d][k] so PV becomes an NT GEMM.
// ---------------------------------------------------------------------------
__global__ __launch_bounds__(256) void vtrans_kernel(const float* __restrict__ qkv,
                                                     float* __restrict__ vt)
{
    __shared__ float tl[32][33];
    int z = blockIdx.z, zb = z >> 4, zh = z & 15;
    int k0 = blockIdx.x * 32, d0 = blockIdx.y * 32;
    int x = threadIdx.x, y = threadIdx.y;   // 32 x 8
#pragma unroll
    for (int i = 0; i < 4; i++) {
        int k = k0 + y + 8 * i;
        tl[y + 8 * i][x] = qkv[((long)(zb * Ss + k)) * TH + 2 * Hh + zh * 64 + d0 + x];
    }
    __syncthreads();
#pragma unroll
    for (int i = 0; i < 4; i++) {
        int d = d0 + y + 8 * i;
        vt[((long)z * 64 + d) * Ss + k0 + x] = tl[x][y + 8 * i];
    }
}

// ---------------------------------------------------------------------------
// Row softmax over g_scores, in place.
// ---------------------------------------------------------------------------
__global__ __launch_bounds__(256) void softmax_kernel(float* __restrict__ sc)
{
    long row = blockIdx.x;
    float4* p = reinterpret_cast<float4*>(sc + row * Ss);
    int tid = threadIdx.x;

    float4 a = p[tid];
    float4 b = p[tid + 256];

    __shared__ float red[8];
    float m = fmaxf(fmaxf(fmaxf(a.x, a.y), fmaxf(a.z, a.w)),
                    fmaxf(fmaxf(b.x, b.y), fmaxf(b.z, b.w)));
#pragma unroll
    for (int o = 16; o; o >>= 1) m = fmaxf(m, __shfl_xor_sync(0xffffffffu, m, o));
    if ((tid & 31) == 0) red[tid >> 5] = m;
    __syncthreads();
    m = red[0];
#pragma unroll
    for (int i = 1; i < 8; i++) m = fmaxf(m, red[i]);
    __syncthreads();

    a.x = expf(a.x - m); a.y = expf(a.y - m); a.z = expf(a.z - m); a.w = expf(a.w - m);
    b.x = expf(b.x - m); b.y = expf(b.y - m); b.z = expf(b.z - m); b.w = expf(b.w - m);

    float s = (a.x + a.y + a.z + a.w) + (b.x + b.y + b.z + b.w);
#pragma unroll
    for (int o = 16; o; o >>= 1) s += __shfl_xor_sync(0xffffffffu, s, o);
    if ((tid & 31) == 0) red[tid >> 5] = s;
    __syncthreads();
    s = 0.f;
#pragma unroll
    for (int i = 0; i < 8; i++) s += red[i];

    float inv = 1.0f / s;
    a.x *= inv; a.y *= inv; a.z *= inv; a.w *= inv;
    b.x *= inv; b.y *= inv; b.z *= inv; b.w *= inv;
    p[tid] = a;
    p[tid + 256] = b;
}

// ---------------------------------------------------------------------------
extern "C" void kernel_launch(void* const* d_in, const int* in_sizes, int n_in,
                              void* d_out, int out_size)
{
    const float* x     = (const float*)d_in[0];   // [2,2048,1024]
    const float* w_qkv = (const float*)d_in[1];   // [3072,1024]
    const float* w_out = (const float*)d_in[2];   // [1024,1024]
    float* out = (float*)d_out;                   // [2,2048,1024]

    float* qkv;  cudaGetSymbolAddress((void**)&qkv,  g_qkv);
    float* sco;  cudaGetSymbolAddress((void**)&sco,  g_scores);
    float* attn; cudaGetSymbolAddress((void**)&attn, g_attn);
    float* vt;   cudaGetSymbolAddress((void**)&vt,   g_vt);

    // 1) qkv = x @ w_qkv^T     (4096 x 3072 x 1024)
    gemm_mma<128><<<dim3(TH / 128, M1 / 128, 1), 256>>>(
        x, w_qkv, qkv, Hh, Hh, Hh, TH,
        0, 0, 0, 0, 0, 0, 1.0f);

    // 2) RoPE on q,k in place
    rope_kernel<<<(Bb * Ss * NHh * 32) / 256, 256>>>(qkv);

    // 3) V transpose (independent of RoPE)
    vtrans_kernel<<<dim3(Ss / 32, 2, NBH), dim3(32, 8)>>>(qkv, vt);

    // 4) scores = 0.125 * Q K^T, batched over 32 (b,h)
    gemm_mma<128><<<dim3(Ss / 128, Ss / 128, NBH), 256>>>(
        qkv, qkv + Hh, sco, HDd, TH, TH, Ss,
        (long)Ss * TH, 64, (long)Ss * TH, 64,
        16L * Ss * Ss, (long)Ss * Ss, 0.125f);

    // 5) softmax rows
    softmax_kernel<<<NBH * Ss, 256>>>(sco);

    // 6) O = P @ Vt^T  (2048 x 64 x 2048 per z)
    gemm_mma<64><<<dim3(1, Ss / 128, NBH), 256>>>(
        sco, vt, attn, Ss, Ss, Ss, Hh,
        16L * Ss * Ss, (long)Ss * Ss,
        16L * 64 * Ss, (long)64 * Ss,
        2048L * 1024, 64, 1.0f);

    // 7) out = attn @ w_out^T  (4096 x 1024 x 1024)
    gemm_mma<128><<<dim3(Hh / 128, M1 / 128, 1), 256>>>(
        attn, w_out, out, Hh, Hh, Hh, Hh,
        0, 0, 0, 0, 0, 0, 1.0f);
}

// round 10
// speedup vs baseline: 1.9743x; 1.1583x over previous
#include <cuda_runtime.h>
#include <cuda_bf16.h>
#include <math.h>
#include <stdint.h>

// Problem constants
#define Bb   2
#define Ss   2048
#define Hh   1024
#define NHh  16
#define HDd  64
#define TH   3072          // 3*H
#define M1   4096          // B*S
#define NBH  32            // B*NH
#define FP   72            // flash smem pitch (64 + 8 pad), bf16 elems

// Scratch (static device globals)
__device__ float g_qkv[(size_t)M1 * TH];                 // 50 MB
__device__ float g_attn[(size_t)M1 * Hh];                // 16 MB
__device__ float g_vt[(size_t)NBH * 64 * Ss];            // 16 MB  V transposed [z][d][k]

// ---------------------------------------------------------------------------
// Helpers
// ---------------------------------------------------------------------------
__device__ __forceinline__ uint32_t smem_u32(const void* p) {
    uint32_t a;
    asm("{ .reg .u64 t; cvta.to.shared.u64 t, %1; cvt.u32.u64 %0, t; }"
        : "=r"(a) : "l"(p));
    return a;
}

__device__ __forceinline__ void ldm4(uint32_t& r0, uint32_t& r1, uint32_t& r2, uint32_t& r3,
                                     uint32_t addr) {
    asm volatile("ldmatrix.sync.aligned.m8n8.x4.shared.b16 {%0,%1,%2,%3}, [%4];"
                 : "=r"(r0), "=r"(r1), "=r"(r2), "=r"(r3) : "r"(addr));
}

__device__ __forceinline__ void mma16816(float* c, const uint32_t* a, const uint32_t* b) {
    asm volatile(
        "mma.sync.aligned.m16n8k16.row.col.f32.bf16.bf16.f32 "
        "{%0,%1,%2,%3}, {%4,%5,%6,%7}, {%8,%9}, {%0,%1,%2,%3};"
        : "+f"(c[0]), "+f"(c[1]), "+f"(c[2]), "+f"(c[3])
        : "r"(a[0]), "r"(a[1]), "r"(a[2]), "r"(a[3]), "r"(b[0]), "r"(b[1]));
}

// fp32 -> (hi,lo) bf16 split of a float4, packed into two uint2 (bf16x2 pairs)
__device__ __forceinline__ void split_f4(float4 v, uint2& hh, uint2& ll) {
    __nv_bfloat16 h0 = __float2bfloat16_rn(v.x), h1 = __float2bfloat16_rn(v.y);
    __nv_bfloat16 h2 = __float2bfloat16_rn(v.z), h3 = __float2bfloat16_rn(v.w);
    __nv_bfloat16 l0 = __float2bfloat16_rn(v.x - __bfloat162float(h0));
    __nv_bfloat16 l1 = __float2bfloat16_rn(v.y - __bfloat162float(h1));
    __nv_bfloat16 l2 = __float2bfloat16_rn(v.z - __bfloat162float(h2));
    __nv_bfloat16 l3 = __float2bfloat16_rn(v.w - __bfloat162float(h3));
    hh.x = ((uint32_t)__bfloat16_as_ushort(h1) << 16) | __bfloat16_as_ushort(h0);
    hh.y = ((uint32_t)__bfloat16_as_ushort(h3) << 16) | __bfloat16_as_ushort(h2);
    ll.x = ((uint32_t)__bfloat16_as_ushort(l1) << 16) | __bfloat16_as_ushort(l0);
    ll.y = ((uint32_t)__bfloat16_as_ushort(l3) << 16) | __bfloat16_as_ushort(l2);
}

__device__ __forceinline__ void splitpair(float a, float b, uint32_t& hi, uint32_t& lo) {
    __nv_bfloat16 ha = __float2bfloat16_rn(a), hb = __float2bfloat16_rn(b);
    __nv_bfloat16 la = __float2bfloat16_rn(a - __bfloat162float(ha));
    __nv_bfloat16 lb = __float2bfloat16_rn(b - __bfloat162float(hb));
    hi = ((uint32_t)__bfloat16_as_ushort(hb) << 16) | __bfloat16_as_ushort(ha);
    lo = ((uint32_t)__bfloat16_as_ushort(lb) << 16) | __bfloat16_as_ushort(la);
}

// ---------------------------------------------------------------------------
// Batched NT GEMM on mma.sync bf16 with 3-term fp32 emulation (proven R6).
// ---------------------------------------------------------------------------
template<int BN>
__global__ __launch_bounds__(256) void gemm_mma(
    const float* __restrict__ A, const float* __restrict__ Bm, float* __restrict__ C,
    int K, int lda, int ldb, int ldc,
    long aOffB, long aOffH, long bOffB, long bOffH, long cOffB, long cOffH,
    float alpha)
{
    constexpr int WN   = BN / 2;
    constexpr int NSUB = BN / 16;
    constexpr int NB4  = BN / 32;
    constexpr int P    = 40;

    __shared__ __align__(16) uint16_t sAhi[128 * P];
    __shared__ __align__(16) uint16_t sAlo[128 * P];
    __shared__ __align__(16) uint16_t sBhi[BN * P];
    __shared__ __align__(16) uint16_t sBlo[BN * P];

    const int tid = threadIdx.x;
    const int t   = tid & 31;
    const int wid = tid >> 5;
    const int warp_m = wid & 3;
    const int warp_n = wid >> 2;

    const int z = blockIdx.z, zb = z >> 4, zh = z & 15;
    const float* At = A + (long)zb * aOffB + (long)zh * aOffH + (long)blockIdx.y * 128 * lda;
    const float* Bt = Bm + (long)zb * bOffB + (long)zh * bOffH + (long)blockIdx.x * BN * ldb;
    float* Cb = C + (long)zb * cOffB + (long)zh * cOffH;

    const uint32_t uAhi = smem_u32(sAhi), uAlo = smem_u32(sAlo);
    const uint32_t uBhi = smem_u32(sBhi), uBlo = smem_u32(sBlo);

    const int aRow = (t & 7) + ((t >> 3) & 1) * 8;
    const int aCol = (t >> 4) << 3;
    const int bRow = (t & 7) + ((t >> 4) << 3);
    const int bCol = ((t >> 3) & 1) << 3;

    float acc[2][NSUB][4];
#pragma unroll
    for (int i = 0; i < 2; i++)
#pragma unroll
        for (int j = 0; j < NSUB; j++)
#pragma unroll
            for (int q = 0; q < 4; q++) acc[i][j][q] = 0.f;

    float4 aPf[4], bPf[NB4];
#pragma unroll
    for (int i = 0; i < 4; i++) {
        int id = tid + 256 * i;
        aPf[i] = *(const float4*)(At + (long)(id >> 3) * lda + ((id & 7) << 2));
    }
#pragma unroll
    for (int i = 0; i < NB4; i++) {
        int id = tid + 256 * i;
        bPf[i] = *(const float4*)(Bt + (long)(id >> 3) * ldb + ((id & 7) << 2));
    }

    const int niter = K / 32;
    for (int it = 0; it < niter; ++it) {
        __syncthreads();
#pragma unroll
        for (int i = 0; i < 4; i++) {
            int id = tid + 256 * i;
            int e = (id >> 3) * P + ((id & 7) << 2);
            uint2 hh, ll;
            split_f4(aPf[i], hh, ll);
            *(uint2*)&sAhi[e] = hh;
            *(uint2*)&sAlo[e] = ll;
        }
#pragma unroll
        for (int i = 0; i < NB4; i++) {
            int id = tid + 256 * i;
            int e = (id >> 3) * P + ((id & 7) << 2);
            uint2 hh, ll;
            split_f4(bPf[i], hh, ll);
            *(uint2*)&sBhi[e] = hh;
            *(uint2*)&sBlo[e] = ll;
        }
        __syncthreads();

        if (it + 1 < niter) {
            const float* An = At + (it + 1) * 32;
            const float* Bn = Bt + (it + 1) * 32;
#pragma unroll
            for (int i = 0; i < 4; i++) {
                int id = tid + 256 * i;
                aPf[i] = *(const float4*)(An + (long)(id >> 3) * lda + ((id & 7) << 2));
            }
#pragma unroll
            for (int i = 0; i < NB4; i++) {
                int id = tid + 256 * i;
                bPf[i] = *(const float4*)(Bn + (long)(id >> 3) * ldb + ((id & 7) << 2));
            }
        }

#pragma unroll
        for (int ks = 0; ks < 2; ks++) {
            const int k0 = ks * 16;
            uint32_t ah[2][4], al[2][4];
#pragma unroll
            for (int ms = 0; ms < 2; ms++) {
                int mbase = warp_m * 32 + ms * 16;
                uint32_t e = (uint32_t)((mbase + aRow) * P + k0 + aCol) * 2;
                ldm4(ah[ms][0], ah[ms][1], ah[ms][2], ah[ms][3], uAhi + e);
                ldm4(al[ms][0], al[ms][1], al[ms][2], al[ms][3], uAlo + e);
            }
            uint32_t bh[NSUB][2], bl[NSUB][2];
#pragma unroll
            for (int p = 0; p < NSUB / 2; p++) {
                int nbase = warp_n * WN + p * 16;
                uint32_t e = (uint32_t)((nbase + bRow) * P + k0 + bCol) * 2;
                ldm4(bh[2 * p][0], bh[2 * p][1], bh[2 * p + 1][0], bh[2 * p + 1][1], uBhi + e);
                ldm4(bl[2 * p][0], bl[2 * p][1], bl[2 * p + 1][0], bl[2 * p + 1][1], uBlo + e);
            }
#pragma unroll
            for (int ms = 0; ms < 2; ms++)
#pragma unroll
                for (int ns = 0; ns < NSUB; ns++) {
                    mma16816(acc[ms][ns], ah[ms], bh[ns]);
                    mma16816(acc[ms][ns], ah[ms], bl[ns]);
                    mma16816(acc[ms][ns], al[ms], bh[ns]);
                }
        }
    }

    const int rBase = blockIdx.y * 128 + warp_m * 32;
    const long cBase = (long)blockIdx.x * BN + warp_n * WN;
#pragma unroll
    for (int ms = 0; ms < 2; ms++) {
        int r0 = rBase + ms * 16 + (t >> 2);
#pragma unroll
        for (int ns = 0; ns < NSUB; ns++) {
            long c0 = cBase + ns * 8 + (t & 3) * 2;
            float2 v0 = make_float2(acc[ms][ns][0] * alpha, acc[ms][ns][1] * alpha);
            float2 v1 = make_float2(acc[ms][ns][2] * alpha, acc[ms][ns][3] * alpha);
            *(float2*)(Cb + (long)r0 * ldc + c0)       = v0;
            *(float2*)(Cb + (long)(r0 + 8) * ldc + c0) = v1;
        }
    }
}

// ---------------------------------------------------------------------------
// Fused flash attention: per CTA 128 q-rows x one (b,h); loops over 32 key
// chunks of 64. S = Q*K^T (Q pre-scaled), online softmax, O += P*V. All MMAs
// use the 3-term bf16-split scheme. P round-trips through SMEM to become
// A-fragments for the PV product.
// ---------------------------------------------------------------------------
__global__ __launch_bounds__(256) void flash_kernel(
    const float* __restrict__ qkv, const float* __restrict__ vt, float* __restrict__ attn)
{
    extern __shared__ char sm[];
    uint16_t* sKhi = (uint16_t*)(sm + 0);       // 64 x FP
    uint16_t* sKlo = (uint16_t*)(sm + 9216);
    uint16_t* sVhi = (uint16_t*)(sm + 18432);   // 64 x FP (Vt: rows d, cols k)
    uint16_t* sVlo = (uint16_t*)(sm + 27648);
    uint16_t* sPhi = (uint16_t*)(sm + 36864);   // 128 x FP (also Q staging)
    uint16_t* sPlo = (uint16_t*)(sm + 55296);

    const int tid = threadIdx.x, t = tid & 31, wid = tid >> 5;
    const int z = blockIdx.y, zb = z >> 4, zh = z & 15;
    const int q0 = blockIdx.x * 128;

    const uint32_t uKhi = smem_u32(sKhi), uKlo = smem_u32(sKlo);
    const uint32_t uVhi = smem_u32(sVhi), uVlo = smem_u32(sVlo);
    const uint32_t uPhi = smem_u32(sPhi), uPlo = smem_u32(sPlo);

    const int aRow = (t & 7) + ((t >> 3) & 1) * 8;
    const int aCol = (t >> 4) << 3;
    const int bRow = (t & 7) + ((t >> 4) << 3);
    const int bCol = ((t >> 3) & 1) << 3;

    // ---- Stage Q (scaled by 1/8) via sP buffers, then ldmatrix into registers
#pragma unroll
    for (int i = 0; i < 8; i++) {
        int id = tid + 256 * i;
        int r = id >> 4, c4 = id & 15;
        float4 v = *(const float4*)(qkv + ((long)(zb * Ss + q0 + r)) * TH + zh * 64 + (c4 << 2));
        v.x *= 0.125f; v.y *= 0.125f; v.z *= 0.125f; v.w *= 0.125f;
        uint2 hh, ll; split_f4(v, hh, ll);
        int e = r * FP + (c4 << 2);
        *(uint2*)&sPhi[e] = hh; *(uint2*)&sPlo[e] = ll;
    }
    __syncthreads();
    uint32_t qh[4][4], ql[4][4];
#pragma unroll
    for (int ks = 0; ks < 4; ks++) {
        uint32_t e = (uint32_t)((wid * 16 + aRow) * FP + ks * 16 + aCol) * 2;
        ldm4(qh[ks][0], qh[ks][1], qh[ks][2], qh[ks][3], uPhi + e);
        ldm4(ql[ks][0], ql[ks][1], ql[ks][2], ql[ks][3], uPlo + e);
    }

    float oacc[8][4];
#pragma unroll
    for (int n = 0; n < 8; n++)
#pragma unroll
        for (int q = 0; q < 4; q++) oacc[n][q] = 0.f;
    float m0 = -1e30f, m1 = -1e30f, l0 = 0.f, l1 = 0.f;

    for (int j = 0; j < 32; j++) {
        __syncthreads();   // previous chunk fully consumed (incl. Q ldmatrix on j==0)

        // Load K chunk [64 keys][64 hd] and V chunk Vt[64 d][64 k]
#pragma unroll
        for (int i = 0; i < 4; i++) {
            int id = tid + 256 * i;
            int r = id >> 4, c4 = id & 15;
            float4 v = *(const float4*)(qkv + ((long)(zb * Ss + j * 64 + r)) * TH + Hh + zh * 64 + (c4 << 2));
            uint2 hh, ll; split_f4(v, hh, ll);
            int e = r * FP + (c4 << 2);
            *(uint2*)&sKhi[e] = hh; *(uint2*)&sKlo[e] = ll;
        }
#pragma unroll
        for (int i = 0; i < 4; i++) {
            int id = tid + 256 * i;
            int r = id >> 4, c4 = id & 15;
            float4 v = *(const float4*)(vt + ((long)z * 64 + r) * Ss + j * 64 + (c4 << 2));
            uint2 hh, ll; split_f4(v, hh, ll);
            int e = r * FP + (c4 << 2);
            *(uint2*)&sVhi[e] = hh; *(uint2*)&sVlo[e] = ll;
        }
        __syncthreads();

        // S = Q * K^T  (pre-scaled)
        float sacc[8][4];
#pragma unroll
        for (int n = 0; n < 8; n++)
#pragma unroll
            for (int q = 0; q < 4; q++) sacc[n][q] = 0.f;
#pragma unroll
        for (int ks = 0; ks < 4; ks++) {
            uint32_t bh[8][2], bl[8][2];
#pragma unroll
            for (int p = 0; p < 4; p++) {
                uint32_t e = (uint32_t)((p * 16 + bRow) * FP + ks * 16 + bCol) * 2;
                ldm4(bh[2 * p][0], bh[2 * p][1], bh[2 * p + 1][0], bh[2 * p + 1][1], uKhi + e);
                ldm4(bl[2 * p][0], bl[2 * p][1], bl[2 * p + 1][0], bl[2 * p + 1][1], uKlo + e);
            }
#pragma unroll
            for (int ns = 0; ns < 8; ns++) {
                mma16816(sacc[ns], qh[ks], bh[ns]);
                mma16816(sacc[ns], qh[ks], bl[ns]);
                mma16816(sacc[ns], ql[ks], bh[ns]);
            }
        }

        // Online softmax. Thread owns rows r0=(t>>2), r1=r0+8 of warp tile.
        float mx0 = -1e30f, mx1 = -1e30f;
#pragma unroll
        for (int ns = 0; ns < 8; ns++) {
            mx0 = fmaxf(mx0, fmaxf(sacc[ns][0], sacc[ns][1]));
            mx1 = fmaxf(mx1, fmaxf(sacc[ns][2], sacc[ns][3]));
        }
        mx0 = fmaxf(mx0, __shfl_xor_sync(0xffffffffu, mx0, 1));
        mx0 = fmaxf(mx0, __shfl_xor_sync(0xffffffffu, mx0, 2));
        mx1 = fmaxf(mx1, __shfl_xor_sync(0xffffffffu, mx1, 1));
        mx1 = fmaxf(mx1, __shfl_xor_sync(0xffffffffu, mx1, 2));
        float mn0 = fmaxf(m0, mx0), mn1 = fmaxf(m1, mx1);
        float c0 = expf(m0 - mn0), c1 = expf(m1 - mn1);
        m0 = mn0; m1 = mn1;

        const int row0 = wid * 16 + (t >> 2);
        const int row1 = row0 + 8;
        float s0 = 0.f, s1 = 0.f;
#pragma unroll
        for (int ns = 0; ns < 8; ns++) {
            float p00 = expf(sacc[ns][0] - mn0);
            float p01 = expf(sacc[ns][1] - mn0);
            float p10 = expf(sacc[ns][2] - mn1);
            float p11 = expf(sacc[ns][3] - mn1);
            s0 += p00 + p01; s1 += p10 + p11;
            int c = ns * 8 + (t & 3) * 2;
            uint32_t hi, lo;
            splitpair(p00, p01, hi, lo);
            *(uint32_t*)&sPhi[row0 * FP + c] = hi;
            *(uint32_t*)&sPlo[row0 * FP + c] = lo;
            splitpair(p10, p11, hi, lo);
            *(uint32_t*)&sPhi[row1 * FP + c] = hi;
            *(uint32_t*)&sPlo[row1 * FP + c] = lo;
            oacc[ns][0] *= c0; oacc[ns][1] *= c0;
            oacc[ns][2] *= c1; oacc[ns][3] *= c1;
        }
        s0 += __shfl_xor_sync(0xffffffffu, s0, 1);
        s0 += __shfl_xor_sync(0xffffffffu, s0, 2);
        s1 += __shfl_xor_sync(0xffffffffu, s1, 1);
        s1 += __shfl_xor_sync(0xffffffffu, s1, 2);
        l0 = l0 * c0 + s0;
        l1 = l1 * c1 + s1;
        __syncwarp();   // P tile (own 16 rows) visible to own warp's ldmatrix

        // O += P * V
#pragma unroll
        for (int ks = 0; ks < 4; ks++) {
            uint32_t ph[4], pl[4];
            uint32_t e = (uint32_t)((wid * 16 + aRow) * FP + ks * 16 + aCol) * 2;
            ldm4(ph[0], ph[1], ph[2], ph[3], uPhi + e);
            ldm4(pl[0], pl[1], pl[2], pl[3], uPlo + e);
            uint32_t vh[8][2], vl[8][2];
#pragma unroll
            for (int p = 0; p < 4; p++) {
                uint32_t ev = (uint32_t)((p * 16 + bRow) * FP + ks * 16 + bCol) * 2;
                ldm4(vh[2 * p][0], vh[2 * p][1], vh[2 * p + 1][0], vh[2 * p + 1][1], uVhi + ev);
                ldm4(vl[2 * p][0], vl[2 * p][1], vl[2 * p + 1][0], vl[2 * p + 1][1], uVlo + ev);
            }
#pragma unroll
            for (int ns = 0; ns < 8; ns++) {
                mma16816(oacc[ns], ph, vh[ns]);
                mma16816(oacc[ns], ph, vl[ns]);
                mma16816(oacc[ns], pl, vh[ns]);
            }
        }
    }

    // Epilogue: O /= l, store to g_attn [B*S][H]
    float inv0 = 1.0f / l0, inv1 = 1.0f / l1;
    long gr0 = (long)(zb * Ss + q0 + wid * 16 + (t >> 2));
    long gr1 = gr0 + 8;
#pragma unroll
    for (int ns = 0; ns < 8; ns++) {
        long c = zh * 64 + ns * 8 + (t & 3) * 2;
        *(float2*)(attn + gr0 * Hh + c) = make_float2(oacc[ns][0] * inv0, oacc[ns][1] * inv0);
        *(float2*)(attn + gr1 * Hh + c) = make_float2(oacc[ns][2] * inv1, oacc[ns][3] * inv1);
    }
}

// ---------------------------------------------------------------------------
// RoPE in-place on q,k inside g_qkv (fp32, mirrors jax fp32 arithmetic).
// ---------------------------------------------------------------------------
__global__ __launch_bounds__(256) void rope_kernel(float* __restrict__ qkv)
{
    int idx = blockIdx.x * blockDim.x + threadIdx.x;
    int d = idx & 31;
    int h = (idx >> 5) & 15;
    int s = (idx >> 9) & 2047;
    int b = idx >> 20;

    float invf = 1.0f / powf(10000.0f, (float)d / 32.0f);
    float phase = (float)s * invf;
    float sn, cs;
    sincosf(phase, &sn, &cs);

    long base = ((long)(b * Ss + s)) * TH + h * 64 + d;
    {
        float x1 = qkv[base];
        float x2 = qkv[base + 32];
        qkv[base]      = x1 * cs - x2 * sn;
        qkv[base + 32] = x2 * cs + x1 * sn;
    }
    {
        float x1 = qkv[base + Hh];
        float x2 = qkv[base + Hh + 32];
        qkv[base + Hh]      = x1 * cs - x2 * sn;
        qkv[base + Hh + 32] = x2 * cs + x1 * sn;
    }
}

// ---------------------------------------------------------------------------
// Transpose V into Vt[z][d][k].
// ---------------------------------------------------------------------------
__global__ __launch_bounds__(256) void vtrans_kernel(const float* __restrict__ qkv,
                                                     float* __restrict__ vt)
{
    __shared__ float tl[32][33];
    int z = blockIdx.z, zb = z >> 4, zh = z & 15;
    int k0 = blockIdx.x * 32, d0 = blockIdx.y * 32;
    int x = threadIdx.x, y = threadIdx.y;   // 32 x 8
#pragma unroll
    for (int i = 0; i < 4; i++) {
        int k = k0 + y + 8 * i;
        tl[y + 8 * i][x] = qkv[((long)(zb * Ss + k)) * TH + 2 * Hh + zh * 64 + d0 + x];
    }
    __syncthreads();
#pragma unroll
    for (int i = 0; i < 4; i++) {
        int d = d0 + y + 8 * i;
        vt[((long)z * 64 + d) * Ss + k0 + x] = tl[x][y + 8 * i];
    }
}

// ---------------------------------------------------------------------------
extern "C" void kernel_launch(void* const* d_in, const int* in_sizes, int n_in,
                              void* d_out, int out_size)
{
    const float* x     = (const float*)d_in[0];   // [2,2048,1024]
    const float* w_qkv = (const float*)d_in[1];   // [3072,1024]
    const float* w_out = (const float*)d_in[2];   // [1024,1024]
    float* out = (float*)d_out;                   // [2,2048,1024]

    float* qkv;  cudaGetSymbolAddress((void**)&qkv,  g_qkv);
    float* attn; cudaGetSymbolAddress((void**)&attn, g_attn);
    float* vt;   cudaGetSymbolAddress((void**)&vt,   g_vt);

    const int FSMEM = 73728;   // 6 buffers (see flash_kernel offsets)
    cudaFuncSetAttribute(flash_kernel, cudaFuncAttributeMaxDynamicSharedMemorySize, FSMEM);

    // 1) qkv = x @ w_qkv^T     (4096 x 3072 x 1024)
    gemm_mma<128><<<dim3(TH / 128, M1 / 128, 1), 256>>>(
        x, w_qkv, qkv, Hh, Hh, Hh, TH,
        0, 0, 0, 0, 0, 0, 1.0f);

    // 2) RoPE on q,k in place
    rope_kernel<<<(Bb * Ss * NHh * 32) / 256, 256>>>(qkv);

    // 3) V transpose
    vtrans_kernel<<<dim3(Ss / 32, 2, NBH), dim3(32, 8)>>>(qkv, vt);

    // 4) Fused attention: scores + softmax + PV
    flash_kernel<<<dim3(Ss / 128, NBH), 256, FSMEM>>>(qkv, vt, attn);

    // 5) out = attn @ w_out^T  (4096 x 1024 x 1024)
    gemm_mma<128><<<dim3(Hh / 128, M1 / 128, 1), 256>>>(
        attn, w_out, out, Hh, Hh, Hh, Hh,
        0, 0, 0, 0, 0, 0, 1.0f);
}

// round 15
// speedup vs baseline: 2.2980x; 1.1639x over previous
#include <cuda_runtime.h>
#include <cuda_bf16.h>
#include <math.h>
#include <stdint.h>

// Problem constants
#define Bb   2
#define Ss   2048
#define Hh   1024
#define NHh  16
#define HDd  64
#define TH   3072          // 3*H
#define M1   4096          // B*S
#define NBH  32            // B*NH
#define FP   72            // flash smem pitch (64 + 8 pad), bf16 elems

// Scratch (static device globals)
__device__ float g_qkv[(size_t)M1 * TH];                  // 50 MB
__device__ float g_attn[(size_t)M1 * Hh];                 // 16 MB
// Pre-split bf16 hi/lo operands for flash ([z][s][d] for Q,K; [z][d][k] for Vt)
__device__ __align__(16) uint16_t g_qh[(size_t)NBH * Ss * 64];
__device__ __align__(16) uint16_t g_ql[(size_t)NBH * Ss * 64];
__device__ __align__(16) uint16_t g_kh[(size_t)NBH * Ss * 64];
__device__ __align__(16) uint16_t g_kl[(size_t)NBH * Ss * 64];
__device__ __align__(16) uint16_t g_vth[(size_t)NBH * 64 * Ss];
__device__ __align__(16) uint16_t g_vtl[(size_t)NBH * 64 * Ss];

// ---------------------------------------------------------------------------
// Helpers
// ---------------------------------------------------------------------------
__device__ __forceinline__ uint32_t smem_u32(const void* p) {
    uint32_t a;
    asm("{ .reg .u64 t; cvta.to.shared.u64 t, %1; cvt.u32.u64 %0, t; }"
        : "=r"(a) : "l"(p));
    return a;
}

__device__ __forceinline__ void ldm4(uint32_t& r0, uint32_t& r1, uint32_t& r2, uint32_t& r3,
                                     uint32_t addr) {
    asm volatile("ldmatrix.sync.aligned.m8n8.x4.shared.b16 {%0,%1,%2,%3}, [%4];"
                 : "=r"(r0), "=r"(r1), "=r"(r2), "=r"(r3) : "r"(addr));
}

__device__ __forceinline__ void mma16816(float* c, const uint32_t* a, const uint32_t* b) {
    asm volatile(
        "mma.sync.aligned.m16n8k16.row.col.f32.bf16.bf16.f32 "
        "{%0,%1,%2,%3}, {%4,%5,%6,%7}, {%8,%9}, {%0,%1,%2,%3};"
        : "+f"(c[0]), "+f"(c[1]), "+f"(c[2]), "+f"(c[3])
        : "r"(a[0]), "r"(a[1]), "r"(a[2]), "r"(a[3]), "r"(b[0]), "r"(b[1]));
}

__device__ __forceinline__ void cpa16(uint32_t s, const void* g) {
    asm volatile("cp.async.cg.shared.global [%0], [%1], 16;"
                 :: "r"(s), "l"(g) : "memory");
}

// fp32 -> (hi,lo) bf16 split of a float4, packed into two uint2 (bf16x2 pairs)
__device__ __forceinline__ void split_f4(float4 v, uint2& hh, uint2& ll) {
    __nv_bfloat16 h0 = __float2bfloat16_rn(v.x), h1 = __float2bfloat16_rn(v.y);
    __nv_bfloat16 h2 = __float2bfloat16_rn(v.z), h3 = __float2bfloat16_rn(v.w);
    __nv_bfloat16 l0 = __float2bfloat16_rn(v.x - __bfloat162float(h0));
    __nv_bfloat16 l1 = __float2bfloat16_rn(v.y - __bfloat162float(h1));
    __nv_bfloat16 l2 = __float2bfloat16_rn(v.z - __bfloat162float(h2));
    __nv_bfloat16 l3 = __float2bfloat16_rn(v.w - __bfloat162float(h3));
    hh.x = ((uint32_t)__bfloat16_as_ushort(h1) << 16) | __bfloat16_as_ushort(h0);
    hh.y = ((uint32_t)__bfloat16_as_ushort(h3) << 16) | __bfloat16_as_ushort(h2);
    ll.x = ((uint32_t)__bfloat16_as_ushort(l1) << 16) | __bfloat16_as_ushort(l0);
    ll.y = ((uint32_t)__bfloat16_as_ushort(l3) << 16) | __bfloat16_as_ushort(l2);
}

__device__ __forceinline__ void splitpair(float a, float b, uint32_t& hi, uint32_t& lo) {
    __nv_bfloat16 ha = __float2bfloat16_rn(a), hb = __float2bfloat16_rn(b);
    __nv_bfloat16 la = __float2bfloat16_rn(a - __bfloat162float(ha));
    __nv_bfloat16 lb = __float2bfloat16_rn(b - __bfloat162float(hb));
    hi = ((uint32_t)__bfloat16_as_ushort(hb) << 16) | __bfloat16_as_ushort(ha);
    lo = ((uint32_t)__bfloat16_as_ushort(lb) << 16) | __bfloat16_as_ushort(la);
}

// ---------------------------------------------------------------------------
// Batched NT GEMM on mma.sync bf16 with 3-term fp32 emulation (proven R6/R10).
// ---------------------------------------------------------------------------
template<int BN>
__global__ __launch_bounds__(256) void gemm_mma(
    const float* __restrict__ A, const float* __restrict__ Bm, float* __restrict__ C,
    int K, int lda, int ldb, int ldc,
    long aOffB, long aOffH, long bOffB, long bOffH, long cOffB, long cOffH,
    float alpha)
{
    constexpr int WN   = BN / 2;
    constexpr int NSUB = BN / 16;
    constexpr int NB4  = BN / 32;
    constexpr int P    = 40;

    __shared__ __align__(16) uint16_t sAhi[128 * P];
    __shared__ __align__(16) uint16_t sAlo[128 * P];
    __shared__ __align__(16) uint16_t sBhi[BN * P];
    __shared__ __align__(16) uint16_t sBlo[BN * P];

    const int tid = threadIdx.x;
    const int t   = tid & 31;
    const int wid = tid >> 5;
    const int warp_m = wid & 3;
    const int warp_n = wid >> 2;

    const int z = blockIdx.z, zb = z >> 4, zh = z & 15;
    const float* At = A + (long)zb * aOffB + (long)zh * aOffH + (long)blockIdx.y * 128 * lda;
    const float* Bt = Bm + (long)zb * bOffB + (long)zh * bOffH + (long)blockIdx.x * BN * ldb;
    float* Cb = C + (long)zb * cOffB + (long)zh * cOffH;

    const uint32_t uAhi = smem_u32(sAhi), uAlo = smem_u32(sAlo);
    const uint32_t uBhi = smem_u32(sBhi), uBlo = smem_u32(sBlo);

    const int aRow = (t & 7) + ((t >> 3) & 1) * 8;
    const int aCol = (t >> 4) << 3;
    const int bRow = (t & 7) + ((t >> 4) << 3);
    const int bCol = ((t >> 3) & 1) << 3;

    float acc[2][NSUB][4];
#pragma unroll
    for (int i = 0; i < 2; i++)
#pragma unroll
        for (int j = 0; j < NSUB; j++)
#pragma unroll
            for (int q = 0; q < 4; q++) acc[i][j][q] = 0.f;

    float4 aPf[4], bPf[NB4];
#pragma unroll
    for (int i = 0; i < 4; i++) {
        int id = tid + 256 * i;
        aPf[i] = *(const float4*)(At + (long)(id >> 3) * lda + ((id & 7) << 2));
    }
#pragma unroll
    for (int i = 0; i < NB4; i++) {
        int id = tid + 256 * i;
        bPf[i] = *(const float4*)(Bt + (long)(id >> 3) * ldb + ((id & 7) << 2));
    }

    const int niter = K / 32;
    for (int it = 0; it < niter; ++it) {
        __syncthreads();
#pragma unroll
        for (int i = 0; i < 4; i++) {
            int id = tid + 256 * i;
            int e = (id >> 3) * P + ((id & 7) << 2);
            uint2 hh, ll;
            split_f4(aPf[i], hh, ll);
            *(uint2*)&sAhi[e] = hh;
            *(uint2*)&sAlo[e] = ll;
        }
#pragma unroll
        for (int i = 0; i < NB4; i++) {
            int id = tid + 256 * i;
            int e = (id >> 3) * P + ((id & 7) << 2);
            uint2 hh, ll;
            split_f4(bPf[i], hh, ll);
            *(uint2*)&sBhi[e] = hh;
            *(uint2*)&sBlo[e] = ll;
        }
        __syncthreads();

        if (it + 1 < niter) {
            const float* An = At + (it + 1) * 32;
            const float* Bn = Bt + (it + 1) * 32;
#pragma unroll
            for (int i = 0; i < 4; i++) {
                int id = tid + 256 * i;
                aPf[i] = *(const float4*)(An + (long)(id >> 3) * lda + ((id & 7) << 2));
            }
#pragma unroll
            for (int i = 0; i < NB4; i++) {
                int id = tid + 256 * i;
                bPf[i] = *(const float4*)(Bn + (long)(id >> 3) * ldb + ((id & 7) << 2));
            }
        }

#pragma unroll
        for (int ks = 0; ks < 2; ks++) {
            const int k0 = ks * 16;
            uint32_t ah[2][4], al[2][4];
#pragma unroll
            for (int ms = 0; ms < 2; ms++) {
                int mbase = warp_m * 32 + ms * 16;
                uint32_t e = (uint32_t)((mbase + aRow) * P + k0 + aCol) * 2;
                ldm4(ah[ms][0], ah[ms][1], ah[ms][2], ah[ms][3], uAhi + e);
                ldm4(al[ms][0], al[ms][1], al[ms][2], al[ms][3], uAlo + e);
            }
            uint32_t bh[NSUB][2], bl[NSUB][2];
#pragma unroll
            for (int p = 0; p < NSUB / 2; p++) {
                int nbase = warp_n * WN + p * 16;
                uint32_t e = (uint32_t)((nbase + bRow) * P + k0 + bCol) * 2;
                ldm4(bh[2 * p][0], bh[2 * p][1], bh[2 * p + 1][0], bh[2 * p + 1][1], uBhi + e);
                ldm4(bl[2 * p][0], bl[2 * p][1], bl[2 * p + 1][0], bl[2 * p + 1][1], uBlo + e);
            }
#pragma unroll
            for (int ms = 0; ms < 2; ms++)
#pragma unroll
                for (int ns = 0; ns < NSUB; ns++) {
                    mma16816(acc[ms][ns], ah[ms], bh[ns]);
                    mma16816(acc[ms][ns], ah[ms], bl[ns]);
                    mma16816(acc[ms][ns], al[ms], bh[ns]);
                }
        }
    }

    const int rBase = blockIdx.y * 128 + warp_m * 32;
    const long cBase = (long)blockIdx.x * BN + warp_n * WN;
#pragma unroll
    for (int ms = 0; ms < 2; ms++) {
        int r0 = rBase + ms * 16 + (t >> 2);
#pragma unroll
        for (int ns = 0; ns < NSUB; ns++) {
            long c0 = cBase + ns * 8 + (t & 3) * 2;
            float2 v0 = make_float2(acc[ms][ns][0] * alpha, acc[ms][ns][1] * alpha);
            float2 v1 = make_float2(acc[ms][ns][2] * alpha, acc[ms][ns][3] * alpha);
            *(float2*)(Cb + (long)r0 * ldc + c0)       = v0;
            *(float2*)(Cb + (long)(r0 + 8) * ldc + c0) = v1;
        }
    }
}

// ---------------------------------------------------------------------------
// RoPE in-place on q,k inside g_qkv (fp32, mirrors jax fp32 arithmetic).
// ---------------------------------------------------------------------------
__global__ __launch_bounds__(256) void rope_kernel(float* __restrict__ qkv)
{
    int idx = blockIdx.x * blockDim.x + threadIdx.x;
    int d = idx & 31;
    int h = (idx >> 5) & 15;
    int s = (idx >> 9) & 2047;
    int b = idx >> 20;

    float invf = 1.0f / powf(10000.0f, (float)d / 32.0f);
    float phase = (float)s * invf;
    float sn, cs;
    sincosf(phase, &sn, &cs);

    long base = ((long)(b * Ss + s)) * TH + h * 64 + d;
    {
        float x1 = qkv[base];
        float x2 = qkv[base + 32];
        qkv[base]      = x1 * cs - x2 * sn;
        qkv[base + 32] = x2 * cs + x1 * sn;
    }
    {
        float x1 = qkv[base + Hh];
        float x2 = qkv[base + Hh + 32];
        qkv[base + Hh]      = x1 * cs - x2 * sn;
        qkv[base + Hh + 32] = x2 * cs + x1 * sn;
    }
}

// ---------------------------------------------------------------------------
// Pre-split Q (scaled 1/8) and K (post-RoPE) into bf16 hi/lo at [z][s][d].
// ---------------------------------------------------------------------------
__global__ __launch_bounds__(256) void qksplit_kernel(
    const float* __restrict__ qkv,
    uint16_t* __restrict__ qh, uint16_t* __restrict__ ql,
    uint16_t* __restrict__ kh, uint16_t* __restrict__ kl)
{
    int idx = blockIdx.x * 256 + threadIdx.x;   // < 2^20
    int d4 = idx & 15;
    int h  = (idx >> 4) & 15;
    int s  = (idx >> 8) & 2047;
    int b  = idx >> 19;
    long in  = ((long)(b * Ss + s)) * TH + h * 64 + (d4 << 2);
    long out = ((long)((b * 16 + h) * Ss + s)) * 64 + (d4 << 2);

    float4 q = *(const float4*)(qkv + in);
    q.x *= 0.125f; q.y *= 0.125f; q.z *= 0.125f; q.w *= 0.125f;
    uint2 hh, ll;
    split_f4(q, hh, ll);
    *(uint2*)(qh + out) = hh;
    *(uint2*)(ql + out) = ll;

    float4 k = *(const float4*)(qkv + in + Hh);
    split_f4(k, hh, ll);
    *(uint2*)(kh + out) = hh;
    *(uint2*)(kl + out) = ll;
}

// ---------------------------------------------------------------------------
// Transpose + split V into bf16 hi/lo Vt[z][d][k].
// ---------------------------------------------------------------------------
__global__ __launch_bounds__(256) void vsplit_kernel(
    const float* __restrict__ qkv,
    uint16_t* __restrict__ vth, uint16_t* __restrict__ vtl)
{
    __shared__ float tl[32][33];
    int z = blockIdx.z, zb = z >> 4, zh = z & 15;
    int k0 = blockIdx.x * 32, d0 = blockIdx.y * 32;
    int x = threadIdx.x, y = threadIdx.y;   // 32 x 8
#pragma unroll
    for (int i = 0; i < 4; i++) {
        int k = k0 + y + 8 * i;
        tl[y + 8 * i][x] = qkv[((long)(zb * Ss + k)) * TH + 2 * Hh + zh * 64 + d0 + x];
    }
    __syncthreads();
#pragma unroll
    for (int i = 0; i < 4; i++) {
        int d = d0 + y + 8 * i;
        float f = tl[x][y + 8 * i];
        __nv_bfloat16 hb = __float2bfloat16_rn(f);
        __nv_bfloat16 lb = __float2bfloat16_rn(f - __bfloat162float(hb));
        long o = ((long)z * 64 + d) * Ss + k0 + x;
        vth[o] = __bfloat16_as_ushort(hb);
        vtl[o] = __bfloat16_as_ushort(lb);
    }
}

// ---------------------------------------------------------------------------
// Fused flash attention v2: pre-split bf16 operands, cp.async 2-stage
// pipeline for K/V chunks, P kept in registers (C-frag == A-frag layout).
// Stage s at smem + s*36864: Khi +0, Klo +9216, Vhi +18432, Vlo +27648.
// ---------------------------------------------------------------------------
__device__ __forceinline__ void flash_issue(
    uint32_t smBase, int stg, int z, int j, int tid,
    const uint16_t* kh_g, const uint16_t* kl_g,
    const uint16_t* vh_g, const uint16_t* vl_g)
{
    uint32_t sb = smBase + stg * 36864;
#pragma unroll
    for (int i = 0; i < 2; i++) {
        int c = tid + 256 * i;              // 0..511
        int r = c >> 3, c16 = c & 7;
        uint32_t so = (uint32_t)(r * FP + c16 * 8) * 2;
        long gk = ((long)(z * Ss + j * 64 + r)) * 64 + c16 * 8;
        long gv = ((long)(z * 64 + r)) * Ss + j * 64 + c16 * 8;
        cpa16(sb + so,         kh_g + gk);
        cpa16(sb + 9216 + so,  kl_g + gk);
        cpa16(sb + 18432 + so, vh_g + gv);
        cpa16(sb + 27648 + so, vl_g + gv);
    }
    asm volatile("cp.async.commit_group;" ::: "memory");
}

__global__ __launch_bounds__(256) void flash_kernel(
    const uint16_t* __restrict__ qh_g, const uint16_t* __restrict__ ql_g,
    const uint16_t* __restrict__ kh_g, const uint16_t* __restrict__ kl_g,
    const uint16_t* __restrict__ vh_g, const uint16_t* __restrict__ vl_g,
    float* __restrict__ attn)
{
    extern __shared__ char sm[];
    const int tid = threadIdx.x, t = tid & 31, wid = tid >> 5;
    const int z = blockIdx.y, zb = z >> 4, zh = z & 15;
    const int q0 = blockIdx.x * 128;
    const uint32_t smBase = smem_u32(sm);

    const int aRow = (t & 7) + ((t >> 3) & 1) * 8;
    const int aCol = (t >> 4) << 3;
    const int bRow = (t & 7) + ((t >> 4) << 3);
    const int bCol = ((t >> 3) & 1) << 3;

    // ---- Stage Q (pre-scaled, pre-split) via cp.async, then ldmatrix
    // Qhi at smBase+0 (128 x FP), Qlo at smBase+18432.
#pragma unroll
    for (int i = 0; i < 4; i++) {
        int c = tid + 256 * i;              // 0..1023
        int r = c >> 3, c16 = c & 7;
        uint32_t so = (uint32_t)(r * FP + c16 * 8) * 2;
        long g = ((long)(z * Ss + q0 + r)) * 64 + c16 * 8;
        cpa16(smBase + so,         qh_g + g);
        cpa16(smBase + 18432 + so, ql_g + g);
    }
    asm volatile("cp.async.commit_group;" ::: "memory");
    asm volatile("cp.async.wait_group 0;" ::: "memory");
    __syncthreads();

    uint32_t qh[4][4], ql[4][4];
#pragma unroll
    for (int ks = 0; ks < 4; ks++) {
        uint32_t e = (uint32_t)((wid * 16 + aRow) * FP + ks * 16 + aCol) * 2;
        ldm4(qh[ks][0], qh[ks][1], qh[ks][2], qh[ks][3], smBase + e);
        ldm4(ql[ks][0], ql[ks][1], ql[ks][2], ql[ks][3], smBase + 18432 + e);
    }
    __syncthreads();   // all warps hold Q; smem reusable for pipeline

    float oacc[8][4];
#pragma unroll
    for (int n = 0; n < 8; n++)
#pragma unroll
        for (int q = 0; q < 4; q++) oacc[n][q] = 0.f;
    float m0 = -1e30f, m1 = -1e30f, l0 = 0.f, l1 = 0.f;

    flash_issue(smBase, 0, z, 0, tid, kh_g, kl_g, vh_g, vl_g);

    for (int j = 0; j < 32; j++) {
        if (j + 1 < 32) {
            flash_issue(smBase, (j + 1) & 1, z, j + 1, tid, kh_g, kl_g, vh_g, vl_g);
            asm volatile("cp.async.wait_group 1;" ::: "memory");
        } else {
            asm volatile("cp.async.wait_group 0;" ::: "memory");
        }
        __syncthreads();

        uint32_t sb = smBase + (j & 1) * 36864;
        uint32_t uKhi = sb, uKlo = sb + 9216, uVhi = sb + 18432, uVlo = sb + 27648;

        // S = Q * K^T  (Q pre-scaled)
        float sacc[8][4];
#pragma unroll
        for (int n = 0; n < 8; n++)
#pragma unroll
            for (int q = 0; q < 4; q++) sacc[n][q] = 0.f;
#pragma unroll
        for (int ks = 0; ks < 4; ks++) {
            uint32_t bh[8][2], bl[8][2];
#pragma unroll
            for (int p = 0; p < 4; p++) {
                uint32_t e = (uint32_t)((p * 16 + bRow) * FP + ks * 16 + bCol) * 2;
                ldm4(bh[2 * p][0], bh[2 * p][1], bh[2 * p + 1][0], bh[2 * p + 1][1], uKhi + e);
                ldm4(bl[2 * p][0], bl[2 * p][1], bl[2 * p + 1][0], bl[2 * p + 1][1], uKlo + e);
            }
#pragma unroll
            for (int ns = 0; ns < 8; ns++) {
                mma16816(sacc[ns], qh[ks], bh[ns]);
                mma16816(sacc[ns], qh[ks], bl[ns]);
                mma16816(sacc[ns], ql[ks], bh[ns]);
            }
        }

        // Online softmax; exps overwrite sacc (becomes P).
        float mx0 = -1e30f, mx1 = -1e30f;
#pragma unroll
        for (int ns = 0; ns < 8; ns++) {
            mx0 = fmaxf(mx0, fmaxf(sacc[ns][0], sacc[ns][1]));
            mx1 = fmaxf(mx1, fmaxf(sacc[ns][2], sacc[ns][3]));
        }
        mx0 = fmaxf(mx0, __shfl_xor_sync(0xffffffffu, mx0, 1));
        mx0 = fmaxf(mx0, __shfl_xor_sync(0xffffffffu, mx0, 2));
        mx1 = fmaxf(mx1, __shfl_xor_sync(0xffffffffu, mx1, 1));
        mx1 = fmaxf(mx1, __shfl_xor_sync(0xffffffffu, mx1, 2));
        float mn0 = fmaxf(m0, mx0), mn1 = fmaxf(m1, mx1);
        float c0 = __expf(m0 - mn0), c1 = __expf(m1 - mn1);
        m0 = mn0; m1 = mn1;

        float s0 = 0.f, s1 = 0.f;
#pragma unroll
        for (int ns = 0; ns < 8; ns++) {
            sacc[ns][0] = __expf(sacc[ns][0] - mn0);
            sacc[ns][1] = __expf(sacc[ns][1] - mn0);
            sacc[ns][2] = __expf(sacc[ns][2] - mn1);
            sacc[ns][3] = __expf(sacc[ns][3] - mn1);
            s0 += sacc[ns][0] + sacc[ns][1];
            s1 += sacc[ns][2] + sacc[ns][3];
            oacc[ns][0] *= c0; oacc[ns][1] *= c0;
            oacc[ns][2] *= c1; oacc[ns][3] *= c1;
        }
        s0 += __shfl_xor_sync(0xffffffffu, s0, 1);
        s0 += __shfl_xor_sync(0xffffffffu, s0, 2);
        s1 += __shfl_xor_sync(0xffffffffu, s1, 1);
        s1 += __shfl_xor_sync(0xffffffffu, s1, 2);
        l0 = l0 * c0 + s0;
        l1 = l1 * c1 + s1;

        // O += P * V : P fragments built in registers (C-frag == A-frag layout)
#pragma unroll
        for (int ks = 0; ks < 4; ks++) {
            uint32_t ph[4], pl[4];
            splitpair(sacc[2 * ks][0],     sacc[2 * ks][1],     ph[0], pl[0]);
            splitpair(sacc[2 * ks][2],     sacc[2 * ks][3],     ph[1], pl[1]);
            splitpair(sacc[2 * ks + 1][0], sacc[2 * ks + 1][1], ph[2], pl[2]);
            splitpair(sacc[2 * ks + 1][2], sacc[2 * ks + 1][3], ph[3], pl[3]);
            uint32_t vh[8][2], vl[8][2];
#pragma unroll
            for (int p = 0; p < 4; p++) {
                uint32_t ev = (uint32_t)((p * 16 + bRow) * FP + ks * 16 + bCol) * 2;
                ldm4(vh[2 * p][0], vh[2 * p][1], vh[2 * p + 1][0], vh[2 * p + 1][1], uVhi + ev);
                ldm4(vl[2 * p][0], vl[2 * p][1], vl[2 * p + 1][0], vl[2 * p + 1][1], uVlo + ev);
            }
#pragma unroll
            for (int ns = 0; ns < 8; ns++) {
                mma16816(oacc[ns], ph, vh[ns]);
                mma16816(oacc[ns], ph, vl[ns]);
                mma16816(oacc[ns], pl, vh[ns]);
            }
        }
        __syncthreads();   // stage fully consumed before next-iter cp.async reuse
    }

    // Epilogue: O /= l, store to g_attn [B*S][H]
    float inv0 = 1.0f / l0, inv1 = 1.0f / l1;
    long gr0 = (long)(zb * Ss + q0 + wid * 16 + (t >> 2));
    long gr1 = gr0 + 8;
#pragma unroll
    for (int ns = 0; ns < 8; ns++) {
        long c = zh * 64 + ns * 8 + (t & 3) * 2;
        *(float2*)(attn + gr0 * Hh + c) = make_float2(oacc[ns][0] * inv0, oacc[ns][1] * inv0);
        *(float2*)(attn + gr1 * Hh + c) = make_float2(oacc[ns][2] * inv1, oacc[ns][3] * inv1);
    }
}

// ---------------------------------------------------------------------------
extern "C" void kernel_launch(void* const* d_in, const int* in_sizes, int n_in,
                              void* d_out, int out_size)
{
    const float* x     = (const float*)d_in[0];   // [2,2048,1024]
    const float* w_qkv = (const float*)d_in[1];   // [3072,1024]
    const float* w_out = (const float*)d_in[2];   // [1024,1024]
    float* out = (float*)d_out;                   // [2,2048,1024]

    float* qkv;  cudaGetSymbolAddress((void**)&qkv,  g_qkv);
    float* attn; cudaGetSymbolAddress((void**)&attn, g_attn);
    uint16_t *qh, *ql, *kh, *kl, *vth, *vtl;
    cudaGetSymbolAddress((void**)&qh,  g_qh);
    cudaGetSymbolAddress((void**)&ql,  g_ql);
    cudaGetSymbolAddress((void**)&kh,  g_kh);
    cudaGetSymbolAddress((void**)&kl,  g_kl);
    cudaGetSymbolAddress((void**)&vth, g_vth);
    cudaGetSymbolAddress((void**)&vtl, g_vtl);

    const int FSMEM = 73728;   // 2 stages x (Khi,Klo,Vhi,Vlo) 9216 each
    cudaFuncSetAttribute(flash_kernel, cudaFuncAttributeMaxDynamicSharedMemorySize, FSMEM);

    // 1) qkv = x @ w_qkv^T     (4096 x 3072 x 1024)
    gemm_mma<128><<<dim3(TH / 128, M1 / 128, 1), 256>>>(
        x, w_qkv, qkv, Hh, Hh, Hh, TH,
        0, 0, 0, 0, 0, 0, 1.0f);

    // 2) RoPE on q,k in place
    rope_kernel<<<(Bb * Ss * NHh * 32) / 256, 256>>>(qkv);

    // 3) Pre-split Q,K (post-RoPE) and V (transposed) into bf16 hi/lo
    qksplit_kernel<<<4096, 256>>>(qkv, qh, ql, kh, kl);
    vsplit_kernel<<<dim3(Ss / 32, 2, NBH), dim3(32, 8)>>>(qkv, vth, vtl);

    // 4) Fused attention: scores + softmax + PV
    flash_kernel<<<dim3(Ss / 128, NBH), 256, FSMEM>>>(qh, ql, kh, kl, vth, vtl, attn);

    // 5) out = attn @ w_out^T  (4096 x 1024 x 1024)
    gemm_mma<128><<<dim3(Hh / 128, M1 / 128, 1), 256>>>(
        attn, w_out, out, Hh, Hh, Hh, Hh,
        0, 0, 0, 0, 0, 0, 1.0f);
}